// round 1
// baseline (speedup 1.0000x reference)
#include <cuda_runtime.h>
#include <math.h>

#define EMBED   512
#define HEADS   8
#define HDIM    64
#define TT      6
#define NNODES  30000
#define NGRAPHS 512
#define M_ROWS  (NNODES * TT)   /* 180000 */
#define NCOLS   1024            /* 512 Q cols + 512 K cols */

/* Scratch: fused Q|K projections, row m = node*6+t, cols 0-511 = Q, 512-1023 = K */
__device__ float g_qk[(size_t)M_ROWS * NCOLS];
__device__ float g_gate[NGRAPHS * TT];

/* ------------------------------------------------------------------ */
/* Kernel 0: gate[g][t] = bg[t] + sum_j ac[g][j] * Wg[t][j]            */
/* ------------------------------------------------------------------ */
__global__ void gate_kernel(const float* __restrict__ ac,
                            const float* __restrict__ Wg,
                            const float* __restrict__ bg) {
    int idx = blockIdx.x * blockDim.x + threadIdx.x;
    if (idx >= NGRAPHS * TT) return;
    int g = idx / TT, t = idx % TT;
    float acc = bg[t];
#pragma unroll
    for (int j = 0; j < 5; j++) acc += ac[g * 5 + j] * Wg[t * 5 + j];
    g_gate[idx] = acc;
}

/* ------------------------------------------------------------------ */
/* Kernel 1: fused Q/K projection GEMM.                                */
/* C[m][j] = sum_k X[m][k] * W[j][k] + bias[j],  W = [Wq ; Wk]         */
/* M=180000, N=1024, K=512. BM=BN=128, BK=16, 8x8 per thread.          */
/* ------------------------------------------------------------------ */
#define BM 128
#define BN 128
#define BK 16

__global__ __launch_bounds__(256, 2)
void qk_gemm(const float* __restrict__ X,
             const float* __restrict__ Wq, const float* __restrict__ bq,
             const float* __restrict__ Wk, const float* __restrict__ bkv) {
    __shared__ float As[BK][BM + 4];
    __shared__ float Bs[BK][BN + 4];

    const int tid = threadIdx.x;
    const int m0 = blockIdx.y * BM;
    const int n0 = blockIdx.x * BN;
    const int ty = tid >> 4;    /* 0..15 */
    const int tx = tid & 15;    /* 0..15 */

    /* load coords: 2 float4 loads each for A and B per thread */
    int lrow[2], lk[2];
#pragma unroll
    for (int i = 0; i < 2; i++) {
        int lin = tid + i * 256;
        lrow[i] = lin >> 2;        /* 0..127 */
        lk[i]   = (lin & 3) * 4;   /* 0,4,8,12 */
    }

    const float* asrc[2];
    bool avalid[2];
    const float* bsrc[2];
#pragma unroll
    for (int i = 0; i < 2; i++) {
        int m = m0 + lrow[i];
        avalid[i] = (m < M_ROWS);
        asrc[i] = X + (size_t)(avalid[i] ? m : (M_ROWS - 1)) * EMBED;
        int j = n0 + lrow[i];
        bsrc[i] = (j < 512) ? (Wq + (size_t)j * 512)
                            : (Wk + (size_t)(j - 512) * 512);
    }

    float acc[8][8];
#pragma unroll
    for (int a = 0; a < 8; a++)
#pragma unroll
        for (int b = 0; b < 8; b++) acc[a][b] = 0.f;

    /* first tile -> smem */
#pragma unroll
    for (int i = 0; i < 2; i++) {
        float4 a = avalid[i] ? *(const float4*)(asrc[i] + lk[i])
                             : make_float4(0.f, 0.f, 0.f, 0.f);
        As[lk[i] + 0][lrow[i]] = a.x;
        As[lk[i] + 1][lrow[i]] = a.y;
        As[lk[i] + 2][lrow[i]] = a.z;
        As[lk[i] + 3][lrow[i]] = a.w;
        float4 b = *(const float4*)(bsrc[i] + lk[i]);
        Bs[lk[i] + 0][lrow[i]] = b.x;
        Bs[lk[i] + 1][lrow[i]] = b.y;
        Bs[lk[i] + 2][lrow[i]] = b.z;
        Bs[lk[i] + 3][lrow[i]] = b.w;
    }
    __syncthreads();

    const int KT = EMBED / BK;   /* 32 */
    float4 pa[2], pb[2];
    for (int kt = 0; kt < KT; kt++) {
        if (kt + 1 < KT) {
            int kofs = (kt + 1) * BK;
#pragma unroll
            for (int i = 0; i < 2; i++) {
                pa[i] = avalid[i] ? *(const float4*)(asrc[i] + kofs + lk[i])
                                  : make_float4(0.f, 0.f, 0.f, 0.f);
                pb[i] = *(const float4*)(bsrc[i] + kofs + lk[i]);
            }
        }
#pragma unroll
        for (int kk = 0; kk < BK; kk++) {
            float af[8], bf[8];
            *(float4*)&af[0] = *(const float4*)&As[kk][ty * 8];
            *(float4*)&af[4] = *(const float4*)&As[kk][ty * 8 + 4];
            *(float4*)&bf[0] = *(const float4*)&Bs[kk][tx * 8];
            *(float4*)&bf[4] = *(const float4*)&Bs[kk][tx * 8 + 4];
#pragma unroll
            for (int ii = 0; ii < 8; ii++)
#pragma unroll
                for (int jj = 0; jj < 8; jj++)
                    acc[ii][jj] += af[ii] * bf[jj];
        }
        __syncthreads();
        if (kt + 1 < KT) {
#pragma unroll
            for (int i = 0; i < 2; i++) {
                As[lk[i] + 0][lrow[i]] = pa[i].x;
                As[lk[i] + 1][lrow[i]] = pa[i].y;
                As[lk[i] + 2][lrow[i]] = pa[i].z;
                As[lk[i] + 3][lrow[i]] = pa[i].w;
                Bs[lk[i] + 0][lrow[i]] = pb[i].x;
                Bs[lk[i] + 1][lrow[i]] = pb[i].y;
                Bs[lk[i] + 2][lrow[i]] = pb[i].z;
                Bs[lk[i] + 3][lrow[i]] = pb[i].w;
            }
            __syncthreads();
        }
    }

    /* epilogue: add bias, store */
    float bias_r[8];
#pragma unroll
    for (int jj = 0; jj < 8; jj++) {
        int col = n0 + tx * 8 + jj;
        bias_r[jj] = (col < 512) ? bq[col] : bkv[col - 512];
    }
#pragma unroll
    for (int ii = 0; ii < 8; ii++) {
        int m = m0 + ty * 8 + ii;
        if (m >= M_ROWS) continue;
        float* orow = g_qk + (size_t)m * NCOLS + n0 + tx * 8;
#pragma unroll
        for (int jj = 0; jj < 8; jj++)
            orow[jj] = acc[ii][jj] + bias_r[jj];
    }
}

/* ------------------------------------------------------------------ */
/* Kernel 2: per-node attention. One block (128 thr) per node.         */
/* ------------------------------------------------------------------ */
#define EPAD (EMBED + 4)

__global__ __launch_bounds__(128)
void attn_kernel(const float* __restrict__ emb,
                 const int* __restrict__ batch,
                 float* __restrict__ out_ctx,
                 float* __restrict__ out_attn) {
    __shared__ float Qs[TT][EPAD];
    __shared__ float Ks[TT][EPAD];
    __shared__ float Vs[TT][EPAD];
    __shared__ float Ssc[HEADS][TT][TT];
    __shared__ float Sat[HEADS][TT][TT];
    __shared__ float Sg[TT];

    const int node = blockIdx.x;
    const int tid = threadIdx.x;

    const float4* qkb = (const float4*)(g_qk + (size_t)node * TT * NCOLS);
    const float4* vb  = (const float4*)(emb + (size_t)node * TT * EMBED);

#pragma unroll
    for (int i = 0; i < 6; i++) {
        int lin = tid + i * 128;     /* 0..767 */
        int t = lin >> 7;            /* row 0..5 */
        int c4 = lin & 127;          /* float4 index 0..127 */
        float4 q = qkb[t * 256 + c4];
        float4 k = qkb[t * 256 + 128 + c4];
        float4 v = vb[t * 128 + c4];
        ((float4*)Qs[t])[c4] = q;
        ((float4*)Ks[t])[c4] = k;
        ((float4*)Vs[t])[c4] = v;
    }
    if (tid < TT) Sg[tid] = g_gate[batch[node] * TT + tid];
    __syncthreads();

    /* scores: 288 (h,t,s) tasks */
    for (int task = tid; task < HEADS * TT * TT; task += 128) {
        int h = task / 36;
        int r = task % 36;
        int t = r / 6, s = r % 6;
        const float4* qp = (const float4*)&Qs[t][h * HDIM];
        const float4* kp = (const float4*)&Ks[s][h * HDIM];
        float a0 = 0.f;
#pragma unroll
        for (int d = 0; d < 16; d++) {
            float4 a = qp[d], b = kp[d];
            a0 += a.x * b.x + a.y * b.y + a.z * b.z + a.w * b.w;
        }
        Ssc[h][t][s] = a0 * 0.125f * Sg[s];
    }
    __syncthreads();

    /* top-4-of-6 by |score| + masked softmax: 48 (h,t) rows */
    if (tid < HEADS * TT) {
        int h = tid / 6, t = tid % 6;
        float sc[6], ab[6];
#pragma unroll
        for (int s = 0; s < 6; s++) {
            sc[s] = Ssc[h][t][s];
            ab[s] = fabsf(sc[s]);
        }
        bool keep[6];
        float mx = -INFINITY;
#pragma unroll
        for (int i = 0; i < 6; i++) {
            int rank = 0;
#pragma unroll
            for (int j = 0; j < 6; j++)
                rank += (ab[j] > ab[i]) || (ab[j] == ab[i] && j < i);
            keep[i] = (rank < 4);
            if (keep[i]) mx = fmaxf(mx, sc[i]);
        }
        float e[6], sum = 0.f;
#pragma unroll
        for (int i = 0; i < 6; i++) {
            e[i] = keep[i] ? expf(sc[i] - mx) : 0.f;
            sum += e[i];
        }
        float inv = 1.0f / sum;
        float* oat = out_attn + (size_t)node * (HEADS * TT * TT) + tid * 6;
#pragma unroll
        for (int i = 0; i < 6; i++) {
            float a = e[i] * inv;
            Sat[h][t][i] = a;
            oat[i] = a;
        }
    }
    __syncthreads();

    /* context: out[t][c] = sum_s attn[h][t][s] * V[s][c], h = c/64 */
    float4* octx = (float4*)(out_ctx + (size_t)node * TT * EMBED);
#pragma unroll
    for (int i = 0; i < 6; i++) {
        int lin = tid + i * 128;
        int t = lin >> 7;
        int c4 = lin & 127;
        int h = c4 >> 4;
        float4 a4 = make_float4(0.f, 0.f, 0.f, 0.f);
#pragma unroll
        for (int s = 0; s < 6; s++) {
            float a = Sat[h][t][s];
            float4 v = ((float4*)Vs[s])[c4];
            a4.x += a * v.x; a4.y += a * v.y;
            a4.z += a * v.z; a4.w += a * v.w;
        }
        octx[t * 128 + c4] = a4;
    }
}

/* ------------------------------------------------------------------ */
extern "C" void kernel_launch(void* const* d_in, const int* in_sizes, int n_in,
                              void* d_out, int out_size) {
    const float* emb   = (const float*)d_in[0];
    const float* ac    = (const float*)d_in[1];
    const float* Wk    = (const float*)d_in[2];
    const float* bk    = (const float*)d_in[3];
    const float* Wq    = (const float*)d_in[4];
    const float* bq    = (const float*)d_in[5];
    const float* Wg    = (const float*)d_in[6];
    const float* bg    = (const float*)d_in[7];
    const int*   batch = (const int*)d_in[8];

    float* out = (float*)d_out;
    float* out_ctx  = out;                                   /* [N,T,512] */
    float* out_attn = out + (size_t)NNODES * TT * EMBED;     /* [N,H,T,T] */

    gate_kernel<<<(NGRAPHS * TT + 255) / 256, 256>>>(ac, Wg, bg);

    dim3 grid(NCOLS / BN, (M_ROWS + BM - 1) / BM);
    qk_gemm<<<grid, 256>>>(emb, Wq, bq, Wk, bk);

    attn_kernel<<<NNODES, 128>>>(emb, batch, out_ctx, out_attn);
}

// round 5
// speedup vs baseline: 1.5030x; 1.5030x over previous
#include <cuda_runtime.h>
#include <cuda_bf16.h>
#include <math.h>
#include <cstdint>

#define EMBED   512
#define HEADS   8
#define HDIM    64
#define TT      6
#define NNODES  30000
#define NGRAPHS 512
#define M_ROWS  (NNODES * TT)   /* 180000 */
#define NCOLS   1024            /* 512 Q cols + 512 K cols */

/* Scratch */
__device__ float g_qk[(size_t)M_ROWS * NCOLS];
__device__ float g_gate[NGRAPHS * TT];
__device__ __nv_bfloat16 g_As[3ull * M_ROWS * EMBED];   /* bf16x3 splits of X  */
__device__ __nv_bfloat16 g_Bs[3ull * NCOLS * EMBED];    /* bf16x3 splits of [Wq;Wk] */

/* ================= helpers ================= */
__device__ __forceinline__ uint32_t smem_u32(const void* p) {
    uint32_t a;
    asm("{ .reg .u64 t; cvta.to.shared.u64 t, %1; cvt.u32.u64 %0, t; }" : "=r"(a) : "l"(p));
    return a;
}
__device__ __forceinline__ void cp16(uint32_t dst, const void* src, bool pred) {
    int sz = pred ? 16 : 0;
    asm volatile("cp.async.cg.shared.global [%0], [%1], 16, %2;"
                 :: "r"(dst), "l"(src), "r"(sz) : "memory");
}
__device__ __forceinline__ void ldsm_x4(uint32_t* r, uint32_t addr) {
    asm volatile("ldmatrix.sync.aligned.m8n8.x4.shared.b16 {%0,%1,%2,%3}, [%4];"
                 : "=r"(r[0]), "=r"(r[1]), "=r"(r[2]), "=r"(r[3]) : "r"(addr));
}
__device__ __forceinline__ void mma_bf16(float* c, const uint32_t* a, const uint32_t* b) {
    asm volatile("mma.sync.aligned.m16n8k16.row.col.f32.bf16.bf16.f32 "
                 "{%0,%1,%2,%3}, {%4,%5,%6,%7}, {%8,%9}, {%0,%1,%2,%3};"
                 : "+f"(c[0]), "+f"(c[1]), "+f"(c[2]), "+f"(c[3])
                 : "r"(a[0]), "r"(a[1]), "r"(a[2]), "r"(a[3]), "r"(b[0]), "r"(b[1]));
}

/* ================= gate ================= */
__global__ void gate_kernel(const float* __restrict__ ac,
                            const float* __restrict__ Wg,
                            const float* __restrict__ bg) {
    int idx = blockIdx.x * blockDim.x + threadIdx.x;
    if (idx >= NGRAPHS * TT) return;
    int g = idx / TT, t = idx % TT;
    float acc = bg[t];
#pragma unroll
    for (int j = 0; j < 5; j++) acc += ac[g * 5 + j] * Wg[t * 5 + j];
    g_gate[idx] = acc;
}

/* ================= bf16x3 split conversion ================= */
__device__ __forceinline__ void split3(float x, __nv_bfloat16& a0, __nv_bfloat16& a1, __nv_bfloat16& a2) {
    a0 = __float2bfloat16(x);
    float r = x - __bfloat162float(a0);
    a1 = __float2bfloat16(r);
    r -= __bfloat162float(a1);
    a2 = __float2bfloat16(r);
}

__global__ void split_A_kernel(const float* __restrict__ X) {
    size_t i = ((size_t)blockIdx.x * blockDim.x + threadIdx.x) * 2;
    if (i >= (size_t)M_ROWS * EMBED) return;
    float2 x = *(const float2*)(X + i);
    __nv_bfloat16 a0, a1, a2, b0, b1, b2;
    split3(x.x, a0, a1, a2);
    split3(x.y, b0, b1, b2);
    const size_t SP = (size_t)M_ROWS * EMBED;
    ((__nv_bfloat162*)(g_As + 0 * SP))[i / 2] = __nv_bfloat162(a0, b0);
    ((__nv_bfloat162*)(g_As + 1 * SP))[i / 2] = __nv_bfloat162(a1, b1);
    ((__nv_bfloat162*)(g_As + 2 * SP))[i / 2] = __nv_bfloat162(a2, b2);
}

__global__ void split_B_kernel(const float* __restrict__ Wq, const float* __restrict__ Wk) {
    size_t i = ((size_t)blockIdx.x * blockDim.x + threadIdx.x) * 2;
    if (i >= (size_t)NCOLS * EMBED) return;
    size_t j = i >> 9;
    size_t k = i & 511;
    const float* src = (j < 512) ? (Wq + j * 512 + k) : (Wk + (j - 512) * 512 + k);
    float2 x = *(const float2*)src;
    __nv_bfloat16 a0, a1, a2, b0, b1, b2;
    split3(x.x, a0, a1, a2);
    split3(x.y, b0, b1, b2);
    const size_t SP = (size_t)NCOLS * EMBED;
    ((__nv_bfloat162*)(g_Bs + 0 * SP))[i / 2] = __nv_bfloat162(a0, b0);
    ((__nv_bfloat162*)(g_Bs + 1 * SP))[i / 2] = __nv_bfloat162(a1, b1);
    ((__nv_bfloat162*)(g_Bs + 2 * SP))[i / 2] = __nv_bfloat162(a2, b2);
}

/* ================= mma.sync bf16x3 GEMM, dual-class accumulation =====
 * c_main accumulates a0*b0 only (fp32-GEMM-class rounding).
 * c_rest accumulates a0*b1 + a1*b0 + a0*b2 + a1*b1 + a2*b0 (all ~2^-9 scale).
 * result = c_main + c_rest + bias  (one merge rounding).
 * BM=128, BN=64, BK=32, 256 threads, warp tile 32x32.                    */
#define BK          32
#define KCHUNKS     (EMBED / BK)        /* 16 */
#define A_TILE_B    (128 * 64)          /* per split */
#define B_TILE_B    (64 * 64)
#define STAGE_B     (3 * A_TILE_B + 3 * B_TILE_B)   /* 36 KB */
#define SMEM_TOTAL  (2 * STAGE_B)                   /* 72 KB */

__device__ __forceinline__ void load_chunk(uint32_t sb, int stage, int kc,
                                           int m0, int n0, int tid) {
    const size_t SPA = (size_t)M_ROWS * EMBED;
    const size_t SPB = (size_t)NCOLS * EMBED;
    uint32_t base = sb + stage * STAGE_B;
#pragma unroll
    for (int i = 0; i < 6; i++) {
        int o = tid + i * 256;
        int split = o >> 9;
        int rem = o & 511;
        int row = rem >> 2;
        int g = rem & 3;
        int gs = g ^ ((row >> 1) & 3);
        int m = m0 + row;
        bool v = (m < M_ROWS);
        const __nv_bfloat16* src = g_As + split * SPA
                                 + (size_t)(v ? m : 0) * EMBED + kc * BK + g * 8;
        cp16(base + split * A_TILE_B + row * 64 + gs * 16, src, v);
    }
#pragma unroll
    for (int i = 0; i < 3; i++) {
        int o = tid + i * 256;
        int split = o >> 8;
        int rem = o & 255;
        int row = rem >> 2;
        int g = rem & 3;
        int gs = g ^ ((row >> 1) & 3);
        const __nv_bfloat16* src = g_Bs + split * SPB
                                 + (size_t)(n0 + row) * EMBED + kc * BK + g * 8;
        cp16(base + 3 * A_TILE_B + split * B_TILE_B + row * 64 + gs * 16, src, true);
    }
    asm volatile("cp.async.commit_group;" ::: "memory");
}

__global__ __launch_bounds__(256, 2)
void qk_gemm_mma(const float* __restrict__ bq, const float* __restrict__ bk) {
    extern __shared__ char smem[];
    uint32_t sb = smem_u32(smem);
    const int tid = threadIdx.x;
    const int wid = tid >> 5;
    const int lane = tid & 31;
    const int m0 = blockIdx.y * 128;
    const int n0 = blockIdx.x * 64;
    const int warp_m = (wid >> 1) * 32;
    const int warp_n = (wid & 1) * 32;

    float c_main[2][4][4];
    float c_rest[2][4][4];
#pragma unroll
    for (int im = 0; im < 2; im++)
#pragma unroll
        for (int jn = 0; jn < 4; jn++)
#pragma unroll
            for (int q = 0; q < 4; q++) { c_main[im][jn][q] = 0.f; c_rest[im][jn][q] = 0.f; }

    load_chunk(sb, 0, 0, m0, n0, tid);
    load_chunk(sb, 1, 1, m0, n0, tid);

    const int a_r = (lane & 7) + ((lane >> 3) & 1) * 8;
    const int a_g = (lane >> 4) & 1;
    const int b_r = (lane & 7) + ((lane >> 4) & 1) * 8;
    const int b_g = (lane >> 3) & 1;

    for (int kc = 0; kc < KCHUNKS; kc++) {
        const int st = kc & 1;
        asm volatile("cp.async.wait_group 1;" ::: "memory");
        __syncthreads();
        const uint32_t abase = sb + st * STAGE_B;
        const uint32_t bbase = abase + 3 * A_TILE_B;

#pragma unroll
        for (int ks = 0; ks < 2; ks++) {
            /* all B splits resident (24 regs) */
            uint32_t bf[3][2][4];
#pragma unroll
            for (int s = 0; s < 3; s++)
#pragma unroll
                for (int j2 = 0; j2 < 2; j2++) {
                    int row = warp_n + j2 * 16 + b_r;
                    int g = ks * 2 + b_g;
                    int gs = g ^ ((row >> 1) & 3);
                    ldsm_x4(bf[s][j2], bbase + s * B_TILE_B + row * 64 + gs * 16);
                }
            /* group products by A split: only one af fragment live */
#pragma unroll
            for (int sa = 0; sa < 3; sa++) {
                uint32_t af[2][4];
#pragma unroll
                for (int im = 0; im < 2; im++) {
                    int row = warp_m + im * 16 + a_r;
                    int g = ks * 2 + a_g;
                    int gs = g ^ ((row >> 1) & 3);
                    ldsm_x4(af[im], abase + sa * A_TILE_B + row * 64 + gs * 16);
                }
                const int nb = (sa == 0) ? 3 : (sa == 1) ? 2 : 1;
#pragma unroll
                for (int sbp = 0; sbp < 3; sbp++) {
                    if (sbp >= nb) continue;
                    float (*C)[4][4] = (sa == 0 && sbp == 0) ? c_main : c_rest;
#pragma unroll
                    for (int im = 0; im < 2; im++)
#pragma unroll
                        for (int jn = 0; jn < 4; jn++)
                            mma_bf16(C[im][jn], af[im], &bf[sbp][jn >> 1][(jn & 1) * 2]);
                }
            }
        }
        __syncthreads();
        if (kc + 2 < KCHUNKS)
            load_chunk(sb, st, kc + 2, m0, n0, tid);
        else
            asm volatile("cp.async.commit_group;" ::: "memory");
    }

    /* epilogue: merge classes, add bias, store float2 pairs */
    const float* bias = (n0 < 512) ? (bq + n0) : (bk + (n0 - 512));
#pragma unroll
    for (int im = 0; im < 2; im++) {
#pragma unroll
        for (int jn = 0; jn < 4; jn++) {
            int col = warp_n + jn * 8 + (lane & 3) * 2;
            float b0 = bias[col], b1 = bias[col + 1];
            int row0 = m0 + warp_m + im * 16 + (lane >> 2);
            if (row0 < M_ROWS) {
                float2 v = make_float2(c_main[im][jn][0] + (c_rest[im][jn][0] + b0),
                                       c_main[im][jn][1] + (c_rest[im][jn][1] + b1));
                *(float2*)(g_qk + (size_t)row0 * NCOLS + n0 + col) = v;
            }
            int row1 = row0 + 8;
            if (row1 < M_ROWS) {
                float2 v = make_float2(c_main[im][jn][2] + (c_rest[im][jn][2] + b0),
                                       c_main[im][jn][3] + (c_rest[im][jn][3] + b1));
                *(float2*)(g_qk + (size_t)row1 * NCOLS + n0 + col) = v;
            }
        }
    }
}

/* ================= attention (unchanged, passing) ================= */
#define EPAD (EMBED + 4)

__global__ __launch_bounds__(128)
void attn_kernel(const float* __restrict__ emb,
                 const int* __restrict__ batch,
                 float* __restrict__ out_ctx,
                 float* __restrict__ out_attn) {
    __shared__ float Qs[TT][EPAD];
    __shared__ float Ks[TT][EPAD];
    __shared__ float Vs[TT][EPAD];
    __shared__ float Ssc[HEADS][TT][TT];
    __shared__ float Sat[HEADS][TT][TT];
    __shared__ float Sg[TT];

    const int node = blockIdx.x;
    const int tid = threadIdx.x;

    const float4* qkb = (const float4*)(g_qk + (size_t)node * TT * NCOLS);
    const float4* vb  = (const float4*)(emb + (size_t)node * TT * EMBED);

#pragma unroll
    for (int i = 0; i < 6; i++) {
        int lin = tid + i * 128;
        int t = lin >> 7;
        int c4 = lin & 127;
        float4 q = qkb[t * 256 + c4];
        float4 k = qkb[t * 256 + 128 + c4];
        float4 v = vb[t * 128 + c4];
        ((float4*)Qs[t])[c4] = q;
        ((float4*)Ks[t])[c4] = k;
        ((float4*)Vs[t])[c4] = v;
    }
    if (tid < TT) Sg[tid] = g_gate[batch[node] * TT + tid];
    __syncthreads();

    for (int task = tid; task < HEADS * TT * TT; task += 128) {
        int h = task / 36;
        int r = task % 36;
        int t = r / 6, s = r % 6;
        const float4* qp = (const float4*)&Qs[t][h * HDIM];
        const float4* kp = (const float4*)&Ks[s][h * HDIM];
        float a0 = 0.f;
#pragma unroll
        for (int d = 0; d < 16; d++) {
            float4 a = qp[d], b = kp[d];
            a0 += a.x * b.x + a.y * b.y + a.z * b.z + a.w * b.w;
        }
        Ssc[h][t][s] = a0 * 0.125f * Sg[s];
    }
    __syncthreads();

    if (tid < HEADS * TT) {
        int h = tid / 6, t = tid % 6;
        float sc[6], ab[6];
#pragma unroll
        for (int s = 0; s < 6; s++) {
            sc[s] = Ssc[h][t][s];
            ab[s] = fabsf(sc[s]);
        }
        bool keep[6];
        float mx = -INFINITY;
#pragma unroll
        for (int i = 0; i < 6; i++) {
            int rank = 0;
#pragma unroll
            for (int j = 0; j < 6; j++)
                rank += (ab[j] > ab[i]) || (ab[j] == ab[i] && j < i);
            keep[i] = (rank < 4);
            if (keep[i]) mx = fmaxf(mx, sc[i]);
        }
        float e[6], sum = 0.f;
#pragma unroll
        for (int i = 0; i < 6; i++) {
            e[i] = keep[i] ? expf(sc[i] - mx) : 0.f;
            sum += e[i];
        }
        float inv = 1.0f / sum;
        float* oat = out_attn + (size_t)node * (HEADS * TT * TT) + tid * 6;
#pragma unroll
        for (int i = 0; i < 6; i++) {
            float a = e[i] * inv;
            Sat[h][t][i] = a;
            oat[i] = a;
        }
    }
    __syncthreads();

    float4* octx = (float4*)(out_ctx + (size_t)node * TT * EMBED);
#pragma unroll
    for (int i = 0; i < 6; i++) {
        int lin = tid + i * 128;
        int t = lin >> 7;
        int c4 = lin & 127;
        int h = c4 >> 4;
        float4 a4 = make_float4(0.f, 0.f, 0.f, 0.f);
#pragma unroll
        for (int s = 0; s < 6; s++) {
            float a = Sat[h][t][s];
            float4 v = ((float4*)Vs[s])[c4];
            a4.x += a * v.x; a4.y += a * v.y;
            a4.z += a * v.z; a4.w += a * v.w;
        }
        octx[t * 128 + c4] = a4;
    }
}

/* ================= launch ================= */
extern "C" void kernel_launch(void* const* d_in, const int* in_sizes, int n_in,
                              void* d_out, int out_size) {
    const float* emb   = (const float*)d_in[0];
    const float* ac    = (const float*)d_in[1];
    const float* Wk    = (const float*)d_in[2];
    const float* bk    = (const float*)d_in[3];
    const float* Wq    = (const float*)d_in[4];
    const float* bq    = (const float*)d_in[5];
    const float* Wg    = (const float*)d_in[6];
    const float* bg    = (const float*)d_in[7];
    const int*   batch = (const int*)d_in[8];

    float* out = (float*)d_out;
    float* out_ctx  = out;
    float* out_attn = out + (size_t)NNODES * TT * EMBED;

    gate_kernel<<<(NGRAPHS * TT + 255) / 256, 256>>>(ac, Wg, bg);
    split_A_kernel<<<(M_ROWS * EMBED / 2 + 255) / 256, 256>>>(emb);
    split_B_kernel<<<(NCOLS * EMBED / 2 + 255) / 256, 256>>>(Wq, Wk);

    cudaFuncSetAttribute(qk_gemm_mma, cudaFuncAttributeMaxDynamicSharedMemorySize, SMEM_TOTAL);
    qk_gemm_mma<<<dim3(NCOLS / 64, (M_ROWS + 127) / 128), 256, SMEM_TOTAL>>>(bq, bk);

    attn_kernel<<<NNODES, 128>>>(emb, batch, out_ctx, out_attn);
}

// round 7
// speedup vs baseline: 2.3581x; 1.5689x over previous
#include <cuda_runtime.h>
#include <cuda_bf16.h>
#include <cuda_fp16.h>
#include <math.h>
#include <cstdint>

#define EMBED   512
#define HEADS   8
#define HDIM    64
#define TT      6
#define NNODES  30000
#define NGRAPHS 512
#define M_ROWS  (NNODES * TT)   /* 180000 */
#define NCOLS   1024            /* 512 Q cols + 512 K cols */

#define RESID_SCALE    2048.0f          /* 2^11 */
#define RESID_INV      4.8828125e-4f    /* 2^-11 */

/* Scratch */
__device__ float g_qk[(size_t)M_ROWS * NCOLS];
__device__ float g_gate[NGRAPHS * TT];
__device__ __half g_As[2ull * M_ROWS * EMBED];   /* fp16 split planes of X  */
__device__ __half g_Bs[2ull * NCOLS * EMBED];    /* fp16 split planes of [Wq;Wk] */

/* ================= helpers ================= */
__device__ __forceinline__ uint32_t smem_u32(const void* p) {
    uint32_t a;
    asm("{ .reg .u64 t; cvta.to.shared.u64 t, %1; cvt.u32.u64 %0, t; }" : "=r"(a) : "l"(p));
    return a;
}
__device__ __forceinline__ void cp16(uint32_t dst, const void* src, bool pred) {
    int sz = pred ? 16 : 0;
    asm volatile("cp.async.cg.shared.global [%0], [%1], 16, %2;"
                 :: "r"(dst), "l"(src), "r"(sz) : "memory");
}
__device__ __forceinline__ void ldsm_x4(uint32_t* r, uint32_t addr) {
    asm volatile("ldmatrix.sync.aligned.m8n8.x4.shared.b16 {%0,%1,%2,%3}, [%4];"
                 : "=r"(r[0]), "=r"(r[1]), "=r"(r[2]), "=r"(r[3]) : "r"(addr));
}
__device__ __forceinline__ void mma_f16(float* c, const uint32_t* a, const uint32_t* b) {
    asm volatile("mma.sync.aligned.m16n8k16.row.col.f32.f16.f16.f32 "
                 "{%0,%1,%2,%3}, {%4,%5,%6,%7}, {%8,%9}, {%0,%1,%2,%3};"
                 : "+f"(c[0]), "+f"(c[1]), "+f"(c[2]), "+f"(c[3])
                 : "r"(a[0]), "r"(a[1]), "r"(a[2]), "r"(a[3]), "r"(b[0]), "r"(b[1]));
}

/* ================= gate ================= */
__global__ void gate_kernel(const float* __restrict__ ac,
                            const float* __restrict__ Wg,
                            const float* __restrict__ bg) {
    int idx = blockIdx.x * blockDim.x + threadIdx.x;
    if (idx >= NGRAPHS * TT) return;
    int g = idx / TT, t = idx % TT;
    float acc = bg[t];
#pragma unroll
    for (int j = 0; j < 5; j++) acc += ac[g * 5 + j] * Wg[t * 5 + j];
    g_gate[idx] = acc;
}

/* ========== fp16x2 RN split with scaled residual plane ==========
 * a0 = RN16(x);  a1' = RN16(2^11 * (x - a0))  (normal-range, no subnormals) */
__device__ __forceinline__ void split2s(float x, __half& a0, __half& a1) {
    a0 = __float2half_rn(x);
    a1 = __float2half_rn((x - __half2float(a0)) * RESID_SCALE);
}

__global__ void split_A_kernel(const float* __restrict__ X) {
    size_t i = ((size_t)blockIdx.x * blockDim.x + threadIdx.x) * 2;
    if (i >= (size_t)M_ROWS * EMBED) return;
    float2 x = *(const float2*)(X + i);
    __half a0, a1, b0, b1;
    split2s(x.x, a0, a1);
    split2s(x.y, b0, b1);
    const size_t SP = (size_t)M_ROWS * EMBED;
    ((__half2*)(g_As + 0 * SP))[i / 2] = __half2(a0, b0);
    ((__half2*)(g_As + 1 * SP))[i / 2] = __half2(a1, b1);
}

__global__ void split_B_kernel(const float* __restrict__ Wq, const float* __restrict__ Wk) {
    size_t i = ((size_t)blockIdx.x * blockDim.x + threadIdx.x) * 2;
    if (i >= (size_t)NCOLS * EMBED) return;
    size_t j = i >> 9;
    size_t k = i & 511;
    const float* src = (j < 512) ? (Wq + j * 512 + k) : (Wk + (j - 512) * 512 + k);
    float2 x = *(const float2*)src;
    __half a0, a1, b0, b1;
    split2s(x.x, a0, a1);
    split2s(x.y, b0, b1);
    const size_t SP = (size_t)NCOLS * EMBED;
    ((__half2*)(g_Bs + 0 * SP))[i / 2] = __half2(a0, b0);
    ((__half2*)(g_Bs + 1 * SP))[i / 2] = __half2(a1, b1);
}

/* ================= mma.sync fp16x2 GEMM, 3 products, dual-class =====
 * c_main: a0*b0.   c_rest: a0*b1' + a1'*b0   (both carry 2^11 factor).
 * result = c_main + (c_rest * 2^-11 + bias).
 * BM=128, BN=64, BK=32, 256 threads, warp tile 32x32, 3-stage pipeline. */
#define BK          32
#define KCHUNKS     (EMBED / BK)        /* 16 */
#define A_TILE_B    (128 * 64)          /* per split: 128 rows x 64 B */
#define B_TILE_B    (64 * 64)
#define STAGE_B     (2 * A_TILE_B + 2 * B_TILE_B)   /* 24 KB */
#define NSTAGE      3
#define SMEM_TOTAL  (NSTAGE * STAGE_B)              /* 72 KB */

__device__ __forceinline__ void load_chunk(uint32_t sb, int stage, int kc,
                                           int m0, int n0, int tid) {
    const size_t SPA = (size_t)M_ROWS * EMBED;
    const size_t SPB = (size_t)NCOLS * EMBED;
    uint32_t base = sb + stage * STAGE_B;
#pragma unroll
    for (int i = 0; i < 4; i++) {
        int o = tid + i * 256;
        int split = o >> 9;
        int rem = o & 511;
        int row = rem >> 2;
        int g = rem & 3;
        int gs = g ^ ((row >> 1) & 3);
        int m = m0 + row;
        bool v = (m < M_ROWS);
        const __half* src = g_As + split * SPA
                          + (size_t)(v ? m : 0) * EMBED + kc * BK + g * 8;
        cp16(base + split * A_TILE_B + row * 64 + gs * 16, src, v);
    }
#pragma unroll
    for (int i = 0; i < 2; i++) {
        int o = tid + i * 256;
        int split = o >> 8;
        int rem = o & 255;
        int row = rem >> 2;
        int g = rem & 3;
        int gs = g ^ ((row >> 1) & 3);
        const __half* src = g_Bs + split * SPB
                          + (size_t)(n0 + row) * EMBED + kc * BK + g * 8;
        cp16(base + 2 * A_TILE_B + split * B_TILE_B + row * 64 + gs * 16, src, true);
    }
    asm volatile("cp.async.commit_group;" ::: "memory");
}

__global__ __launch_bounds__(256, 2)
void qk_gemm_mma(const float* __restrict__ bq, const float* __restrict__ bk) {
    extern __shared__ char smem[];
    uint32_t sb = smem_u32(smem);
    const int tid = threadIdx.x;
    const int wid = tid >> 5;
    const int lane = tid & 31;
    const int m0 = blockIdx.y * 128;
    const int n0 = blockIdx.x * 64;
    const int warp_m = (wid >> 1) * 32;
    const int warp_n = (wid & 1) * 32;

    float c_main[2][4][4];
    float c_rest[2][4][4];
#pragma unroll
    for (int im = 0; im < 2; im++)
#pragma unroll
        for (int jn = 0; jn < 4; jn++)
#pragma unroll
            for (int q = 0; q < 4; q++) { c_main[im][jn][q] = 0.f; c_rest[im][jn][q] = 0.f; }

    load_chunk(sb, 0, 0, m0, n0, tid);
    load_chunk(sb, 1, 1, m0, n0, tid);
    load_chunk(sb, 2, 2, m0, n0, tid);

    const int a_r = (lane & 7) + ((lane >> 3) & 1) * 8;
    const int a_g = (lane >> 4) & 1;
    const int b_r = (lane & 7) + ((lane >> 4) & 1) * 8;
    const int b_g = (lane >> 3) & 1;

    for (int kc = 0; kc < KCHUNKS; kc++) {
        const int st = kc % NSTAGE;
        asm volatile("cp.async.wait_group 2;" ::: "memory");
        __syncthreads();
        const uint32_t abase = sb + st * STAGE_B;
        const uint32_t bbase = abase + 2 * A_TILE_B;

#pragma unroll
        for (int ks = 0; ks < 2; ks++) {
            /* both B splits resident (16 regs) */
            uint32_t bf[2][2][4];
#pragma unroll
            for (int s = 0; s < 2; s++)
#pragma unroll
                for (int j2 = 0; j2 < 2; j2++) {
                    int row = warp_n + j2 * 16 + b_r;
                    int g = ks * 2 + b_g;
                    int gs = g ^ ((row >> 1) & 3);
                    ldsm_x4(bf[s][j2], bbase + s * B_TILE_B + row * 64 + gs * 16);
                }
            /* sa=0: a0 tiles -> a0b0 (main), a0b1' (rest) */
            {
                uint32_t af[2][4];
#pragma unroll
                for (int im = 0; im < 2; im++) {
                    int row = warp_m + im * 16 + a_r;
                    int g = ks * 2 + a_g;
                    int gs = g ^ ((row >> 1) & 3);
                    ldsm_x4(af[im], abase + 0 * A_TILE_B + row * 64 + gs * 16);
                }
#pragma unroll
                for (int im = 0; im < 2; im++)
#pragma unroll
                    for (int jn = 0; jn < 4; jn++)
                        mma_f16(c_main[im][jn], af[im], &bf[0][jn >> 1][(jn & 1) * 2]);
#pragma unroll
                for (int im = 0; im < 2; im++)
#pragma unroll
                    for (int jn = 0; jn < 4; jn++)
                        mma_f16(c_rest[im][jn], af[im], &bf[1][jn >> 1][(jn & 1) * 2]);
            }
            /* sa=1: a1' tiles -> a1'b0 (rest) */
            {
                uint32_t af[2][4];
#pragma unroll
                for (int im = 0; im < 2; im++) {
                    int row = warp_m + im * 16 + a_r;
                    int g = ks * 2 + a_g;
                    int gs = g ^ ((row >> 1) & 3);
                    ldsm_x4(af[im], abase + 1 * A_TILE_B + row * 64 + gs * 16);
                }
#pragma unroll
                for (int im = 0; im < 2; im++)
#pragma unroll
                    for (int jn = 0; jn < 4; jn++)
                        mma_f16(c_rest[im][jn], af[im], &bf[0][jn >> 1][(jn & 1) * 2]);
            }
        }
        __syncthreads();
        if (kc + NSTAGE < KCHUNKS)
            load_chunk(sb, st, kc + NSTAGE, m0, n0, tid);
        else
            asm volatile("cp.async.commit_group;" ::: "memory");
    }

    /* epilogue: result = c_main + (c_rest * 2^-11 + bias) */
    const float* bias = (n0 < 512) ? (bq + n0) : (bk + (n0 - 512));
#pragma unroll
    for (int im = 0; im < 2; im++) {
#pragma unroll
        for (int jn = 0; jn < 4; jn++) {
            int col = warp_n + jn * 8 + (lane & 3) * 2;
            float b0 = bias[col], b1 = bias[col + 1];
            int row0 = m0 + warp_m + im * 16 + (lane >> 2);
            if (row0 < M_ROWS) {
                float2 v = make_float2(
                    c_main[im][jn][0] + fmaf(c_rest[im][jn][0], RESID_INV, b0),
                    c_main[im][jn][1] + fmaf(c_rest[im][jn][1], RESID_INV, b1));
                *(float2*)(g_qk + (size_t)row0 * NCOLS + n0 + col) = v;
            }
            int row1 = row0 + 8;
            if (row1 < M_ROWS) {
                float2 v = make_float2(
                    c_main[im][jn][2] + fmaf(c_rest[im][jn][2], RESID_INV, b0),
                    c_main[im][jn][3] + fmaf(c_rest[im][jn][3], RESID_INV, b1));
                *(float2*)(g_qk + (size_t)row1 * NCOLS + n0 + col) = v;
            }
        }
    }
}

/* ================= attention (unchanged, passing) ================= */
#define EPAD (EMBED + 4)

__global__ __launch_bounds__(128)
void attn_kernel(const float* __restrict__ emb,
                 const int* __restrict__ batch,
                 float* __restrict__ out_ctx,
                 float* __restrict__ out_attn) {
    __shared__ float Qs[TT][EPAD];
    __shared__ float Ks[TT][EPAD];
    __shared__ float Vs[TT][EPAD];
    __shared__ float Ssc[HEADS][TT][TT];
    __shared__ float Sat[HEADS][TT][TT];
    __shared__ float Sg[TT];

    const int node = blockIdx.x;
    const int tid = threadIdx.x;

    const float4* qkb = (const float4*)(g_qk + (size_t)node * TT * NCOLS);
    const float4* vb  = (const float4*)(emb + (size_t)node * TT * EMBED);

#pragma unroll
    for (int i = 0; i < 6; i++) {
        int lin = tid + i * 128;
        int t = lin >> 7;
        int c4 = lin & 127;
        float4 q = qkb[t * 256 + c4];
        float4 k = qkb[t * 256 + 128 + c4];
        float4 v = vb[t * 128 + c4];
        ((float4*)Qs[t])[c4] = q;
        ((float4*)Ks[t])[c4] = k;
        ((float4*)Vs[t])[c4] = v;
    }
    if (tid < TT) Sg[tid] = g_gate[batch[node] * TT + tid];
    __syncthreads();

    for (int task = tid; task < HEADS * TT * TT; task += 128) {
        int h = task / 36;
        int r = task % 36;
        int t = r / 6, s = r % 6;
        const float4* qp = (const float4*)&Qs[t][h * HDIM];
        const float4* kp = (const float4*)&Ks[s][h * HDIM];
        float a0 = 0.f;
#pragma unroll
        for (int d = 0; d < 16; d++) {
            float4 a = qp[d], b = kp[d];
            a0 += a.x * b.x + a.y * b.y + a.z * b.z + a.w * b.w;
        }
        Ssc[h][t][s] = a0 * 0.125f * Sg[s];
    }
    __syncthreads();

    if (tid < HEADS * TT) {
        int h = tid / 6, t = tid % 6;
        float sc[6], ab[6];
#pragma unroll
        for (int s = 0; s < 6; s++) {
            sc[s] = Ssc[h][t][s];
            ab[s] = fabsf(sc[s]);
        }
        bool keep[6];
        float mx = -INFINITY;
#pragma unroll
        for (int i = 0; i < 6; i++) {
            int rank = 0;
#pragma unroll
            for (int j = 0; j < 6; j++)
                rank += (ab[j] > ab[i]) || (ab[j] == ab[i] && j < i);
            keep[i] = (rank < 4);
            if (keep[i]) mx = fmaxf(mx, sc[i]);
        }
        float e[6], sum = 0.f;
#pragma unroll
        for (int i = 0; i < 6; i++) {
            e[i] = keep[i] ? expf(sc[i] - mx) : 0.f;
            sum += e[i];
        }
        float inv = 1.0f / sum;
        float* oat = out_attn + (size_t)node * (HEADS * TT * TT) + tid * 6;
#pragma unroll
        for (int i = 0; i < 6; i++) {
            float a = e[i] * inv;
            Sat[h][t][i] = a;
            oat[i] = a;
        }
    }
    __syncthreads();

    float4* octx = (float4*)(out_ctx + (size_t)node * TT * EMBED);
#pragma unroll
    for (int i = 0; i < 6; i++) {
        int lin = tid + i * 128;
        int t = lin >> 7;
        int c4 = lin & 127;
        int h = c4 >> 4;
        float4 a4 = make_float4(0.f, 0.f, 0.f, 0.f);
#pragma unroll
        for (int s = 0; s < 6; s++) {
            float a = Sat[h][t][s];
            float4 v = ((float4*)Vs[s])[c4];
            a4.x += a * v.x; a4.y += a * v.y;
            a4.z += a * v.z; a4.w += a * v.w;
        }
        octx[t * 128 + c4] = a4;
    }
}

/* ================= launch ================= */
extern "C" void kernel_launch(void* const* d_in, const int* in_sizes, int n_in,
                              void* d_out, int out_size) {
    const float* emb   = (const float*)d_in[0];
    const float* ac    = (const float*)d_in[1];
    const float* Wk    = (const float*)d_in[2];
    const float* bk    = (const float*)d_in[3];
    const float* Wq    = (const float*)d_in[4];
    const float* bq    = (const float*)d_in[5];
    const float* Wg    = (const float*)d_in[6];
    const float* bg    = (const float*)d_in[7];
    const int*   batch = (const int*)d_in[8];

    float* out = (float*)d_out;
    float* out_ctx  = out;
    float* out_attn = out + (size_t)NNODES * TT * EMBED;

    gate_kernel<<<(NGRAPHS * TT + 255) / 256, 256>>>(ac, Wg, bg);
    split_A_kernel<<<(M_ROWS * EMBED / 2 + 255) / 256, 256>>>(emb);
    split_B_kernel<<<(NCOLS * EMBED / 2 + 255) / 256, 256>>>(Wq, Wk);

    cudaFuncSetAttribute(qk_gemm_mma, cudaFuncAttributeMaxDynamicSharedMemorySize, SMEM_TOTAL);
    qk_gemm_mma<<<dim3(NCOLS / 64, (M_ROWS + 127) / 128), 256, SMEM_TOTAL>>>(bq, bk);

    attn_kernel<<<NNODES, 128>>>(emb, batch, out_ctx, out_attn);
}

// round 8
// speedup vs baseline: 2.4064x; 1.0205x over previous
#include <cuda_runtime.h>
#include <cuda_bf16.h>
#include <cuda_fp16.h>
#include <math.h>
#include <cstdint>

#define EMBED   512
#define HEADS   8
#define HDIM    64
#define TT      6
#define NNODES  30000
#define NGRAPHS 512
#define M_ROWS  (NNODES * TT)   /* 180000 */
#define NCOLS   1024            /* 512 Q cols + 512 K cols */

#define RESID_SCALE    2048.0f          /* 2^11 */
#define RESID_INV      4.8828125e-4f    /* 2^-11 */

/* Scratch */
__device__ float g_qk[(size_t)M_ROWS * NCOLS];
__device__ float g_gate[NGRAPHS * TT];
__device__ __half g_As[2ull * M_ROWS * EMBED];   /* fp16 split planes of X  */
__device__ __half g_Bs[2ull * NCOLS * EMBED];    /* fp16 split planes of [Wq;Wk] */

/* ================= helpers ================= */
__device__ __forceinline__ uint32_t smem_u32(const void* p) {
    uint32_t a;
    asm("{ .reg .u64 t; cvta.to.shared.u64 t, %1; cvt.u32.u64 %0, t; }" : "=r"(a) : "l"(p));
    return a;
}
__device__ __forceinline__ void cp16(uint32_t dst, const void* src, bool pred) {
    int sz = pred ? 16 : 0;
    asm volatile("cp.async.cg.shared.global [%0], [%1], 16, %2;"
                 :: "r"(dst), "l"(src), "r"(sz) : "memory");
}
__device__ __forceinline__ void ldsm_x4(uint32_t* r, uint32_t addr) {
    asm volatile("ldmatrix.sync.aligned.m8n8.x4.shared.b16 {%0,%1,%2,%3}, [%4];"
                 : "=r"(r[0]), "=r"(r[1]), "=r"(r[2]), "=r"(r[3]) : "r"(addr));
}
__device__ __forceinline__ void mma_f16(float* c, const uint32_t* a, const uint32_t* b) {
    asm volatile("mma.sync.aligned.m16n8k16.row.col.f32.f16.f16.f32 "
                 "{%0,%1,%2,%3}, {%4,%5,%6,%7}, {%8,%9}, {%0,%1,%2,%3};"
                 : "+f"(c[0]), "+f"(c[1]), "+f"(c[2]), "+f"(c[3])
                 : "r"(a[0]), "r"(a[1]), "r"(a[2]), "r"(a[3]), "r"(b[0]), "r"(b[1]));
}

/* ================= gate ================= */
__global__ void gate_kernel(const float* __restrict__ ac,
                            const float* __restrict__ Wg,
                            const float* __restrict__ bg) {
    int idx = blockIdx.x * blockDim.x + threadIdx.x;
    if (idx >= NGRAPHS * TT) return;
    int g = idx / TT, t = idx % TT;
    float acc = bg[t];
#pragma unroll
    for (int j = 0; j < 5; j++) acc += ac[g * 5 + j] * Wg[t * 5 + j];
    g_gate[idx] = acc;
}

/* ========== fp16x2 RN split with scaled residual plane ==========
 * a0 = RN16(x);  a1' = RN16(2^11 * (x - a0))  (normal-range, no subnormals) */
__device__ __forceinline__ void split2s(float x, __half& a0, __half& a1) {
    a0 = __float2half_rn(x);
    a1 = __float2half_rn((x - __half2float(a0)) * RESID_SCALE);
}

__global__ void split_A_kernel(const float* __restrict__ X) {
    size_t i = ((size_t)blockIdx.x * blockDim.x + threadIdx.x) * 2;
    if (i >= (size_t)M_ROWS * EMBED) return;
    float2 x = *(const float2*)(X + i);
    __half a0, a1, b0, b1;
    split2s(x.x, a0, a1);
    split2s(x.y, b0, b1);
    const size_t SP = (size_t)M_ROWS * EMBED;
    ((__half2*)(g_As + 0 * SP))[i / 2] = __half2(a0, b0);
    ((__half2*)(g_As + 1 * SP))[i / 2] = __half2(a1, b1);
}

__global__ void split_B_kernel(const float* __restrict__ Wq, const float* __restrict__ Wk) {
    size_t i = ((size_t)blockIdx.x * blockDim.x + threadIdx.x) * 2;
    if (i >= (size_t)NCOLS * EMBED) return;
    size_t j = i >> 9;
    size_t k = i & 511;
    const float* src = (j < 512) ? (Wq + j * 512 + k) : (Wk + (j - 512) * 512 + k);
    float2 x = *(const float2*)src;
    __half a0, a1, b0, b1;
    split2s(x.x, a0, a1);
    split2s(x.y, b0, b1);
    const size_t SP = (size_t)NCOLS * EMBED;
    ((__half2*)(g_Bs + 0 * SP))[i / 2] = __half2(a0, b0);
    ((__half2*)(g_Bs + 1 * SP))[i / 2] = __half2(a1, b1);
}

/* ================= mma.sync fp16x2 GEMM, 3 products, dual-class =====
 * c_main: a0*b0.   c_rest: a0*b1' + a1'*b0   (both carry 2^11 factor).
 * result = c_main + (c_rest * 2^-11 + bias).
 * BM=128, BN=64, BK=32, 256 threads, warp tile 32x32.
 * 4-stage cp.async pipeline, single __syncthreads per k-chunk.           */
#define BK          32
#define KCHUNKS     (EMBED / BK)        /* 16 */
#define A_TILE_B    (128 * 64)          /* per split: 128 rows x 64 B */
#define B_TILE_B    (64 * 64)
#define STAGE_B     (2 * A_TILE_B + 2 * B_TILE_B)   /* 24 KB */
#define NSTAGE      4
#define SMEM_TOTAL  (NSTAGE * STAGE_B)              /* 96 KB */

__device__ __forceinline__ void load_chunk(uint32_t sb, int stage, int kc,
                                           int m0, int n0, int tid) {
    const size_t SPA = (size_t)M_ROWS * EMBED;
    const size_t SPB = (size_t)NCOLS * EMBED;
    uint32_t base = sb + stage * STAGE_B;
#pragma unroll
    for (int i = 0; i < 4; i++) {
        int o = tid + i * 256;
        int split = o >> 9;
        int rem = o & 511;
        int row = rem >> 2;
        int g = rem & 3;
        int gs = g ^ ((row >> 1) & 3);
        int m = m0 + row;
        bool v = (m < M_ROWS);
        const __half* src = g_As + split * SPA
                          + (size_t)(v ? m : 0) * EMBED + kc * BK + g * 8;
        cp16(base + split * A_TILE_B + row * 64 + gs * 16, src, v);
    }
#pragma unroll
    for (int i = 0; i < 2; i++) {
        int o = tid + i * 256;
        int split = o >> 8;
        int rem = o & 255;
        int row = rem >> 2;
        int g = rem & 3;
        int gs = g ^ ((row >> 1) & 3);
        const __half* src = g_Bs + split * SPB
                          + (size_t)(n0 + row) * EMBED + kc * BK + g * 8;
        cp16(base + 2 * A_TILE_B + split * B_TILE_B + row * 64 + gs * 16, src, true);
    }
    asm volatile("cp.async.commit_group;" ::: "memory");
}

__global__ __launch_bounds__(256, 2)
void qk_gemm_mma(const float* __restrict__ bq, const float* __restrict__ bk) {
    extern __shared__ char smem[];
    uint32_t sb = smem_u32(smem);
    const int tid = threadIdx.x;
    const int wid = tid >> 5;
    const int lane = tid & 31;
    const int m0 = blockIdx.y * 128;
    const int n0 = blockIdx.x * 64;
    const int warp_m = (wid >> 1) * 32;
    const int warp_n = (wid & 1) * 32;

    float c_main[2][4][4];
    float c_rest[2][4][4];
#pragma unroll
    for (int im = 0; im < 2; im++)
#pragma unroll
        for (int jn = 0; jn < 4; jn++)
#pragma unroll
            for (int q = 0; q < 4; q++) { c_main[im][jn][q] = 0.f; c_rest[im][jn][q] = 0.f; }

    /* prologue: NSTAGE-1 = 3 chunks in flight */
    load_chunk(sb, 0, 0, m0, n0, tid);
    load_chunk(sb, 1, 1, m0, n0, tid);
    load_chunk(sb, 2, 2, m0, n0, tid);

    const int a_r = (lane & 7) + ((lane >> 3) & 1) * 8;
    const int a_g = (lane >> 4) & 1;
    const int b_r = (lane & 7) + ((lane >> 4) & 1) * 8;
    const int b_g = (lane >> 3) & 1;

    for (int kc = 0; kc < KCHUNKS; kc++) {
        const int st = kc % NSTAGE;
        /* stage kc ready when <=2 groups outstanding */
        asm volatile("cp.async.wait_group 2;" ::: "memory");
        __syncthreads();   /* also guarantees all warps done reading stage kc-1 */

        /* prefetch chunk kc+3 into the slot stage kc-1 just vacated */
        if (kc + NSTAGE - 1 < KCHUNKS)
            load_chunk(sb, (kc + NSTAGE - 1) % NSTAGE, kc + NSTAGE - 1, m0, n0, tid);
        else
            asm volatile("cp.async.commit_group;" ::: "memory");

        const uint32_t abase = sb + st * STAGE_B;
        const uint32_t bbase = abase + 2 * A_TILE_B;

#pragma unroll
        for (int ks = 0; ks < 2; ks++) {
            /* both B splits resident (16 regs) */
            uint32_t bf[2][2][4];
#pragma unroll
            for (int s = 0; s < 2; s++)
#pragma unroll
                for (int j2 = 0; j2 < 2; j2++) {
                    int row = warp_n + j2 * 16 + b_r;
                    int g = ks * 2 + b_g;
                    int gs = g ^ ((row >> 1) & 3);
                    ldsm_x4(bf[s][j2], bbase + s * B_TILE_B + row * 64 + gs * 16);
                }
            /* sa=0: a0 tiles -> a0b0 (main), a0b1' (rest) */
            {
                uint32_t af[2][4];
#pragma unroll
                for (int im = 0; im < 2; im++) {
                    int row = warp_m + im * 16 + a_r;
                    int g = ks * 2 + a_g;
                    int gs = g ^ ((row >> 1) & 3);
                    ldsm_x4(af[im], abase + 0 * A_TILE_B + row * 64 + gs * 16);
                }
#pragma unroll
                for (int im = 0; im < 2; im++)
#pragma unroll
                    for (int jn = 0; jn < 4; jn++)
                        mma_f16(c_main[im][jn], af[im], &bf[0][jn >> 1][(jn & 1) * 2]);
#pragma unroll
                for (int im = 0; im < 2; im++)
#pragma unroll
                    for (int jn = 0; jn < 4; jn++)
                        mma_f16(c_rest[im][jn], af[im], &bf[1][jn >> 1][(jn & 1) * 2]);
            }
            /* sa=1: a1' tiles -> a1'b0 (rest) */
            {
                uint32_t af[2][4];
#pragma unroll
                for (int im = 0; im < 2; im++) {
                    int row = warp_m + im * 16 + a_r;
                    int g = ks * 2 + a_g;
                    int gs = g ^ ((row >> 1) & 3);
                    ldsm_x4(af[im], abase + 1 * A_TILE_B + row * 64 + gs * 16);
                }
#pragma unroll
                for (int im = 0; im < 2; im++)
#pragma unroll
                    for (int jn = 0; jn < 4; jn++)
                        mma_f16(c_rest[im][jn], af[im], &bf[0][jn >> 1][(jn & 1) * 2]);
            }
        }
    }

    /* epilogue: result = c_main + (c_rest * 2^-11 + bias) */
    const float* bias = (n0 < 512) ? (bq + n0) : (bk + (n0 - 512));
#pragma unroll
    for (int im = 0; im < 2; im++) {
#pragma unroll
        for (int jn = 0; jn < 4; jn++) {
            int col = warp_n + jn * 8 + (lane & 3) * 2;
            float b0 = bias[col], b1 = bias[col + 1];
            int row0 = m0 + warp_m + im * 16 + (lane >> 2);
            if (row0 < M_ROWS) {
                float2 v = make_float2(
                    c_main[im][jn][0] + fmaf(c_rest[im][jn][0], RESID_INV, b0),
                    c_main[im][jn][1] + fmaf(c_rest[im][jn][1], RESID_INV, b1));
                *(float2*)(g_qk + (size_t)row0 * NCOLS + n0 + col) = v;
            }
            int row1 = row0 + 8;
            if (row1 < M_ROWS) {
                float2 v = make_float2(
                    c_main[im][jn][2] + fmaf(c_rest[im][jn][2], RESID_INV, b0),
                    c_main[im][jn][3] + fmaf(c_rest[im][jn][3], RESID_INV, b1));
                *(float2*)(g_qk + (size_t)row1 * NCOLS + n0 + col) = v;
            }
        }
    }
}

/* ================= attention (unchanged, passing) ================= */
#define EPAD (EMBED + 4)

__global__ __launch_bounds__(128)
void attn_kernel(const float* __restrict__ emb,
                 const int* __restrict__ batch,
                 float* __restrict__ out_ctx,
                 float* __restrict__ out_attn) {
    __shared__ float Qs[TT][EPAD];
    __shared__ float Ks[TT][EPAD];
    __shared__ float Vs[TT][EPAD];
    __shared__ float Ssc[HEADS][TT][TT];
    __shared__ float Sat[HEADS][TT][TT];
    __shared__ float Sg[TT];

    const int node = blockIdx.x;
    const int tid = threadIdx.x;

    const float4* qkb = (const float4*)(g_qk + (size_t)node * TT * NCOLS);
    const float4* vb  = (const float4*)(emb + (size_t)node * TT * EMBED);

#pragma unroll
    for (int i = 0; i < 6; i++) {
        int lin = tid + i * 128;
        int t = lin >> 7;
        int c4 = lin & 127;
        float4 q = qkb[t * 256 + c4];
        float4 k = qkb[t * 256 + 128 + c4];
        float4 v = vb[t * 128 + c4];
        ((float4*)Qs[t])[c4] = q;
        ((float4*)Ks[t])[c4] = k;
        ((float4*)Vs[t])[c4] = v;
    }
    if (tid < TT) Sg[tid] = g_gate[batch[node] * TT + tid];
    __syncthreads();

    for (int task = tid; task < HEADS * TT * TT; task += 128) {
        int h = task / 36;
        int r = task % 36;
        int t = r / 6, s = r % 6;
        const float4* qp = (const float4*)&Qs[t][h * HDIM];
        const float4* kp = (const float4*)&Ks[s][h * HDIM];
        float a0 = 0.f;
#pragma unroll
        for (int d = 0; d < 16; d++) {
            float4 a = qp[d], b = kp[d];
            a0 += a.x * b.x + a.y * b.y + a.z * b.z + a.w * b.w;
        }
        Ssc[h][t][s] = a0 * 0.125f * Sg[s];
    }
    __syncthreads();

    if (tid < HEADS * TT) {
        int h = tid / 6, t = tid % 6;
        float sc[6], ab[6];
#pragma unroll
        for (int s = 0; s < 6; s++) {
            sc[s] = Ssc[h][t][s];
            ab[s] = fabsf(sc[s]);
        }
        bool keep[6];
        float mx = -INFINITY;
#pragma unroll
        for (int i = 0; i < 6; i++) {
            int rank = 0;
#pragma unroll
            for (int j = 0; j < 6; j++)
                rank += (ab[j] > ab[i]) || (ab[j] == ab[i] && j < i);
            keep[i] = (rank < 4);
            if (keep[i]) mx = fmaxf(mx, sc[i]);
        }
        float e[6], sum = 0.f;
#pragma unroll
        for (int i = 0; i < 6; i++) {
            e[i] = keep[i] ? expf(sc[i] - mx) : 0.f;
            sum += e[i];
        }
        float inv = 1.0f / sum;
        float* oat = out_attn + (size_t)node * (HEADS * TT * TT) + tid * 6;
#pragma unroll
        for (int i = 0; i < 6; i++) {
            float a = e[i] * inv;
            Sat[h][t][i] = a;
            oat[i] = a;
        }
    }
    __syncthreads();

    float4* octx = (float4*)(out_ctx + (size_t)node * TT * EMBED);
#pragma unroll
    for (int i = 0; i < 6; i++) {
        int lin = tid + i * 128;
        int t = lin >> 7;
        int c4 = lin & 127;
        int h = c4 >> 4;
        float4 a4 = make_float4(0.f, 0.f, 0.f, 0.f);
#pragma unroll
        for (int s = 0; s < 6; s++) {
            float a = Sat[h][t][s];
            float4 v = ((float4*)Vs[s])[c4];
            a4.x += a * v.x; a4.y += a * v.y;
            a4.z += a * v.z; a4.w += a * v.w;
        }
        octx[t * 128 + c4] = a4;
    }
}

/* ================= launch ================= */
extern "C" void kernel_launch(void* const* d_in, const int* in_sizes, int n_in,
                              void* d_out, int out_size) {
    const float* emb   = (const float*)d_in[0];
    const float* ac    = (const float*)d_in[1];
    const float* Wk    = (const float*)d_in[2];
    const float* bk    = (const float*)d_in[3];
    const float* Wq    = (const float*)d_in[4];
    const float* bq    = (const float*)d_in[5];
    const float* Wg    = (const float*)d_in[6];
    const float* bg    = (const float*)d_in[7];
    const int*   batch = (const int*)d_in[8];

    float* out = (float*)d_out;
    float* out_ctx  = out;
    float* out_attn = out + (size_t)NNODES * TT * EMBED;

    gate_kernel<<<(NGRAPHS * TT + 255) / 256, 256>>>(ac, Wg, bg);
    split_A_kernel<<<(M_ROWS * EMBED / 2 + 255) / 256, 256>>>(emb);
    split_B_kernel<<<(NCOLS * EMBED / 2 + 255) / 256, 256>>>(Wq, Wk);

    cudaFuncSetAttribute(qk_gemm_mma, cudaFuncAttributeMaxDynamicSharedMemorySize, SMEM_TOTAL);
    qk_gemm_mma<<<dim3(NCOLS / 64, (M_ROWS + 127) / 128), 256, SMEM_TOTAL>>>(bq, bk);

    attn_kernel<<<NNODES, 128>>>(emb, batch, out_ctx, out_attn);
}

// round 9
// speedup vs baseline: 2.4826x; 1.0317x over previous
#include <cuda_runtime.h>
#include <cuda_bf16.h>
#include <cuda_fp16.h>
#include <math.h>
#include <cstdint>

#define EMBED   512
#define HEADS   8
#define HDIM    64
#define TT      6
#define NNODES  30000
#define NGRAPHS 512
#define M_ROWS  (NNODES * TT)   /* 180000 */
#define NCOLS   1024            /* 512 Q cols + 512 K cols */

#define RESID_SCALE    2048.0f          /* 2^11 */
#define RESID_INV      4.8828125e-4f    /* 2^-11 */

/* Scratch */
__device__ float g_qk[(size_t)M_ROWS * NCOLS];
__device__ __half g_As[2ull * M_ROWS * EMBED];   /* fp16 split planes of X  */
__device__ __half g_Bs[2ull * NCOLS * EMBED];    /* fp16 split planes of [Wq;Wk] */

/* ================= helpers ================= */
__device__ __forceinline__ uint32_t smem_u32(const void* p) {
    uint32_t a;
    asm("{ .reg .u64 t; cvta.to.shared.u64 t, %1; cvt.u32.u64 %0, t; }" : "=r"(a) : "l"(p));
    return a;
}
__device__ __forceinline__ void cp16(uint32_t dst, const void* src, bool pred) {
    int sz = pred ? 16 : 0;
    asm volatile("cp.async.cg.shared.global [%0], [%1], 16, %2;"
                 :: "r"(dst), "l"(src), "r"(sz) : "memory");
}
__device__ __forceinline__ void ldsm_x4(uint32_t* r, uint32_t addr) {
    asm volatile("ldmatrix.sync.aligned.m8n8.x4.shared.b16 {%0,%1,%2,%3}, [%4];"
                 : "=r"(r[0]), "=r"(r[1]), "=r"(r[2]), "=r"(r[3]) : "r"(addr));
}
__device__ __forceinline__ void mma_f16(float* c, const uint32_t* a, const uint32_t* b) {
    asm volatile("mma.sync.aligned.m16n8k16.row.col.f32.f16.f16.f32 "
                 "{%0,%1,%2,%3}, {%4,%5,%6,%7}, {%8,%9}, {%0,%1,%2,%3};"
                 : "+f"(c[0]), "+f"(c[1]), "+f"(c[2]), "+f"(c[3])
                 : "r"(a[0]), "r"(a[1]), "r"(a[2]), "r"(a[3]), "r"(b[0]), "r"(b[1]));
}

/* ========== fp16x2 RN split with scaled residual plane ==========
 * a0 = RN16(x);  a1' = RN16(2^11 * (x - a0))  (normal-range, no subnormals) */
__device__ __forceinline__ void split2s(float x, __half& a0, __half& a1) {
    a0 = __float2half_rn(x);
    a1 = __float2half_rn((x - __half2float(a0)) * RESID_SCALE);
}

/* ================= merged split kernel (A then B) ================= */
#define A_PAIRS ((size_t)M_ROWS * EMBED / 2)   /* 46,080,000 */
#define B_PAIRS ((size_t)NCOLS * EMBED / 2)    /* 262,144 */

__global__ void split_kernel(const float* __restrict__ X,
                             const float* __restrict__ Wq,
                             const float* __restrict__ Wk) {
    size_t gid = (size_t)blockIdx.x * blockDim.x + threadIdx.x;
    if (gid < A_PAIRS) {
        size_t i = gid * 2;
        float2 x = *(const float2*)(X + i);
        __half a0, a1, b0, b1;
        split2s(x.x, a0, a1);
        split2s(x.y, b0, b1);
        const size_t SP = (size_t)M_ROWS * EMBED;
        ((__half2*)(g_As + 0 * SP))[gid] = __half2(a0, b0);
        ((__half2*)(g_As + 1 * SP))[gid] = __half2(a1, b1);
    } else if (gid < A_PAIRS + B_PAIRS) {
        size_t p = gid - A_PAIRS;
        size_t i = p * 2;
        size_t j = i >> 9;
        size_t k = i & 511;
        const float* src = (j < 512) ? (Wq + j * 512 + k) : (Wk + (j - 512) * 512 + k);
        float2 x = *(const float2*)src;
        __half a0, a1, b0, b1;
        split2s(x.x, a0, a1);
        split2s(x.y, b0, b1);
        const size_t SP = (size_t)NCOLS * EMBED;
        ((__half2*)(g_Bs + 0 * SP))[p] = __half2(a0, b0);
        ((__half2*)(g_Bs + 1 * SP))[p] = __half2(a1, b1);
    }
}

/* ================= mma.sync fp16x2 GEMM, 3 products, dual-class =====
 * c_main: a0*b0.   c_rest: a0*b1' + a1'*b0   (both carry 2^11 factor).
 * result = c_main + (c_rest * 2^-11 + bias).
 * BM=64, BN=64, BK=32. 128 threads (4 warps, 2x2 warp grid, tile 32x32).
 * 3-stage cp.async pipeline, 4 CTAs/SM for barrier-latency hiding.      */
#define BK          32
#define KCHUNKS     (EMBED / BK)        /* 16 */
#define A_TILE_B    (64 * 64)           /* per split: 64 rows x 64 B */
#define B_TILE_B    (64 * 64)
#define STAGE_B     (2 * A_TILE_B + 2 * B_TILE_B)   /* 16 KB */
#define NSTAGE      3
#define SMEM_TOTAL  (NSTAGE * STAGE_B)              /* 48 KB */

__device__ __forceinline__ void load_chunk(uint32_t sb, int stage, int kc,
                                           int m0, int n0, int tid) {
    const size_t SPA = (size_t)M_ROWS * EMBED;
    const size_t SPB = (size_t)NCOLS * EMBED;
    uint32_t base = sb + stage * STAGE_B;
    /* A: 2 splits x 64 rows x 4 granules = 512 cp16 ops */
#pragma unroll
    for (int i = 0; i < 4; i++) {
        int o = tid + i * 128;
        int split = o >> 8;
        int rem = o & 255;
        int row = rem >> 2;
        int g = rem & 3;
        int gs = g ^ ((row >> 1) & 3);
        int m = m0 + row;
        bool v = (m < M_ROWS);
        const __half* src = g_As + split * SPA
                          + (size_t)(v ? m : 0) * EMBED + kc * BK + g * 8;
        cp16(base + split * A_TILE_B + row * 64 + gs * 16, src, v);
    }
    /* B: 2 splits x 64 rows x 4 granules = 512 ops */
#pragma unroll
    for (int i = 0; i < 4; i++) {
        int o = tid + i * 128;
        int split = o >> 8;
        int rem = o & 255;
        int row = rem >> 2;
        int g = rem & 3;
        int gs = g ^ ((row >> 1) & 3);
        const __half* src = g_Bs + split * SPB
                          + (size_t)(n0 + row) * EMBED + kc * BK + g * 8;
        cp16(base + 2 * A_TILE_B + split * B_TILE_B + row * 64 + gs * 16, src, true);
    }
    asm volatile("cp.async.commit_group;" ::: "memory");
}

__global__ __launch_bounds__(128, 4)
void qk_gemm_mma(const float* __restrict__ bq, const float* __restrict__ bk) {
    extern __shared__ char smem[];
    uint32_t sb = smem_u32(smem);
    const int tid = threadIdx.x;
    const int wid = tid >> 5;
    const int lane = tid & 31;
    const int m0 = blockIdx.y * 64;
    const int n0 = blockIdx.x * 64;
    const int warp_m = (wid >> 1) * 32;
    const int warp_n = (wid & 1) * 32;

    float c_main[2][4][4];
    float c_rest[2][4][4];
#pragma unroll
    for (int im = 0; im < 2; im++)
#pragma unroll
        for (int jn = 0; jn < 4; jn++)
#pragma unroll
            for (int q = 0; q < 4; q++) { c_main[im][jn][q] = 0.f; c_rest[im][jn][q] = 0.f; }

    /* prologue: NSTAGE-1 = 2 chunks in flight */
    load_chunk(sb, 0, 0, m0, n0, tid);
    load_chunk(sb, 1, 1, m0, n0, tid);

    const int a_r = (lane & 7) + ((lane >> 3) & 1) * 8;
    const int a_g = (lane >> 4) & 1;
    const int b_r = (lane & 7) + ((lane >> 4) & 1) * 8;
    const int b_g = (lane >> 3) & 1;

    for (int kc = 0; kc < KCHUNKS; kc++) {
        const int st = kc % NSTAGE;
        asm volatile("cp.async.wait_group 1;" ::: "memory");
        __syncthreads();   /* stage kc ready; all warps done reading stage kc-1 */

        /* prefetch chunk kc+2 into the slot stage kc-1 just vacated */
        if (kc + NSTAGE - 1 < KCHUNKS)
            load_chunk(sb, (kc + NSTAGE - 1) % NSTAGE, kc + NSTAGE - 1, m0, n0, tid);
        else
            asm volatile("cp.async.commit_group;" ::: "memory");

        const uint32_t abase = sb + st * STAGE_B;
        const uint32_t bbase = abase + 2 * A_TILE_B;

#pragma unroll
        for (int ks = 0; ks < 2; ks++) {
            /* both B splits resident (16 regs) */
            uint32_t bf[2][2][4];
#pragma unroll
            for (int s = 0; s < 2; s++)
#pragma unroll
                for (int j2 = 0; j2 < 2; j2++) {
                    int row = warp_n + j2 * 16 + b_r;
                    int g = ks * 2 + b_g;
                    int gs = g ^ ((row >> 1) & 3);
                    ldsm_x4(bf[s][j2], bbase + s * B_TILE_B + row * 64 + gs * 16);
                }
            /* sa=0: a0 tiles -> a0b0 (main), a0b1' (rest) */
            {
                uint32_t af[2][4];
#pragma unroll
                for (int im = 0; im < 2; im++) {
                    int row = warp_m + im * 16 + a_r;
                    int g = ks * 2 + a_g;
                    int gs = g ^ ((row >> 1) & 3);
                    ldsm_x4(af[im], abase + 0 * A_TILE_B + row * 64 + gs * 16);
                }
#pragma unroll
                for (int im = 0; im < 2; im++)
#pragma unroll
                    for (int jn = 0; jn < 4; jn++)
                        mma_f16(c_main[im][jn], af[im], &bf[0][jn >> 1][(jn & 1) * 2]);
#pragma unroll
                for (int im = 0; im < 2; im++)
#pragma unroll
                    for (int jn = 0; jn < 4; jn++)
                        mma_f16(c_rest[im][jn], af[im], &bf[1][jn >> 1][(jn & 1) * 2]);
            }
            /* sa=1: a1' tiles -> a1'b0 (rest) */
            {
                uint32_t af[2][4];
#pragma unroll
                for (int im = 0; im < 2; im++) {
                    int row = warp_m + im * 16 + a_r;
                    int g = ks * 2 + a_g;
                    int gs = g ^ ((row >> 1) & 3);
                    ldsm_x4(af[im], abase + 1 * A_TILE_B + row * 64 + gs * 16);
                }
#pragma unroll
                for (int im = 0; im < 2; im++)
#pragma unroll
                    for (int jn = 0; jn < 4; jn++)
                        mma_f16(c_rest[im][jn], af[im], &bf[0][jn >> 1][(jn & 1) * 2]);
            }
        }
    }

    /* epilogue: result = c_main + (c_rest * 2^-11 + bias) */
    const float* bias = (n0 < 512) ? (bq + n0) : (bk + (n0 - 512));
#pragma unroll
    for (int im = 0; im < 2; im++) {
#pragma unroll
        for (int jn = 0; jn < 4; jn++) {
            int col = warp_n + jn * 8 + (lane & 3) * 2;
            float b0 = bias[col], b1 = bias[col + 1];
            int row0 = m0 + warp_m + im * 16 + (lane >> 2);
            if (row0 < M_ROWS) {
                float2 v = make_float2(
                    c_main[im][jn][0] + fmaf(c_rest[im][jn][0], RESID_INV, b0),
                    c_main[im][jn][1] + fmaf(c_rest[im][jn][1], RESID_INV, b1));
                *(float2*)(g_qk + (size_t)row0 * NCOLS + n0 + col) = v;
            }
            int row1 = row0 + 8;
            if (row1 < M_ROWS) {
                float2 v = make_float2(
                    c_main[im][jn][2] + fmaf(c_rest[im][jn][2], RESID_INV, b0),
                    c_main[im][jn][3] + fmaf(c_rest[im][jn][3], RESID_INV, b1));
                *(float2*)(g_qk + (size_t)row1 * NCOLS + n0 + col) = v;
            }
        }
    }
}

/* ================= attention (gate inlined) ================= */
#define EPAD (EMBED + 4)

__global__ __launch_bounds__(128)
void attn_kernel(const float* __restrict__ emb,
                 const float* __restrict__ ac,
                 const float* __restrict__ Wg,
                 const float* __restrict__ bg,
                 const int* __restrict__ batch,
                 float* __restrict__ out_ctx,
                 float* __restrict__ out_attn) {
    __shared__ float Qs[TT][EPAD];
    __shared__ float Ks[TT][EPAD];
    __shared__ float Vs[TT][EPAD];
    __shared__ float Ssc[HEADS][TT][TT];
    __shared__ float Sat[HEADS][TT][TT];
    __shared__ float Sg[TT];

    const int node = blockIdx.x;
    const int tid = threadIdx.x;

    const float4* qkb = (const float4*)(g_qk + (size_t)node * TT * NCOLS);
    const float4* vb  = (const float4*)(emb + (size_t)node * TT * EMBED);

#pragma unroll
    for (int i = 0; i < 6; i++) {
        int lin = tid + i * 128;
        int t = lin >> 7;
        int c4 = lin & 127;
        float4 q = qkb[t * 256 + c4];
        float4 k = qkb[t * 256 + 128 + c4];
        float4 v = vb[t * 128 + c4];
        ((float4*)Qs[t])[c4] = q;
        ((float4*)Ks[t])[c4] = k;
        ((float4*)Vs[t])[c4] = v;
    }
    if (tid < TT) {
        int g = batch[node];
        float acc = bg[tid];
#pragma unroll
        for (int j = 0; j < 5; j++) acc += ac[g * 5 + j] * Wg[tid * 5 + j];
        Sg[tid] = acc;
    }
    __syncthreads();

    for (int task = tid; task < HEADS * TT * TT; task += 128) {
        int h = task / 36;
        int r = task % 36;
        int t = r / 6, s = r % 6;
        const float4* qp = (const float4*)&Qs[t][h * HDIM];
        const float4* kp = (const float4*)&Ks[s][h * HDIM];
        float a0 = 0.f;
#pragma unroll
        for (int d = 0; d < 16; d++) {
            float4 a = qp[d], b = kp[d];
            a0 += a.x * b.x + a.y * b.y + a.z * b.z + a.w * b.w;
        }
        Ssc[h][t][s] = a0 * 0.125f * Sg[s];
    }
    __syncthreads();

    if (tid < HEADS * TT) {
        int h = tid / 6, t = tid % 6;
        float sc[6], ab[6];
#pragma unroll
        for (int s = 0; s < 6; s++) {
            sc[s] = Ssc[h][t][s];
            ab[s] = fabsf(sc[s]);
        }
        bool keep[6];
        float mx = -INFINITY;
#pragma unroll
        for (int i = 0; i < 6; i++) {
            int rank = 0;
#pragma unroll
            for (int j = 0; j < 6; j++)
                rank += (ab[j] > ab[i]) || (ab[j] == ab[i] && j < i);
            keep[i] = (rank < 4);
            if (keep[i]) mx = fmaxf(mx, sc[i]);
        }
        float e[6], sum = 0.f;
#pragma unroll
        for (int i = 0; i < 6; i++) {
            e[i] = keep[i] ? expf(sc[i] - mx) : 0.f;
            sum += e[i];
        }
        float inv = 1.0f / sum;
        float* oat = out_attn + (size_t)node * (HEADS * TT * TT) + tid * 6;
#pragma unroll
        for (int i = 0; i < 6; i++) {
            float a = e[i] * inv;
            Sat[h][t][i] = a;
            oat[i] = a;
        }
    }
    __syncthreads();

    float4* octx = (float4*)(out_ctx + (size_t)node * TT * EMBED);
#pragma unroll
    for (int i = 0; i < 6; i++) {
        int lin = tid + i * 128;
        int t = lin >> 7;
        int c4 = lin & 127;
        int h = c4 >> 4;
        float4 a4 = make_float4(0.f, 0.f, 0.f, 0.f);
#pragma unroll
        for (int s = 0; s < 6; s++) {
            float a = Sat[h][t][s];
            float4 v = ((float4*)Vs[s])[c4];
            a4.x += a * v.x; a4.y += a * v.y;
            a4.z += a * v.z; a4.w += a * v.w;
        }
        octx[t * 128 + c4] = a4;
    }
}

/* ================= launch ================= */
extern "C" void kernel_launch(void* const* d_in, const int* in_sizes, int n_in,
                              void* d_out, int out_size) {
    const float* emb   = (const float*)d_in[0];
    const float* ac    = (const float*)d_in[1];
    const float* Wk    = (const float*)d_in[2];
    const float* bk    = (const float*)d_in[3];
    const float* Wq    = (const float*)d_in[4];
    const float* bq    = (const float*)d_in[5];
    const float* Wg    = (const float*)d_in[6];
    const float* bg    = (const float*)d_in[7];
    const int*   batch = (const int*)d_in[8];

    float* out = (float*)d_out;
    float* out_ctx  = out;
    float* out_attn = out + (size_t)NNODES * TT * EMBED;

    size_t tot_pairs = A_PAIRS + B_PAIRS;
    split_kernel<<<(unsigned)((tot_pairs + 255) / 256), 256>>>(emb, Wq, Wk);

    cudaFuncSetAttribute(qk_gemm_mma, cudaFuncAttributeMaxDynamicSharedMemorySize, SMEM_TOTAL);
    qk_gemm_mma<<<dim3(NCOLS / 64, (M_ROWS + 63) / 64), 128, SMEM_TOTAL>>>(bq, bk);

    attn_kernel<<<NNODES, 128>>>(emb, ac, Wg, bg, batch, out_ctx, out_attn);
}

// round 10
// speedup vs baseline: 2.6546x; 1.0693x over previous
#include <cuda_runtime.h>
#include <cuda_bf16.h>
#include <cuda_fp16.h>
#include <math.h>
#include <cstdint>

#define EMBED   512
#define HEADS   8
#define HDIM    64
#define TT      6
#define NNODES  30000
#define NGRAPHS 512
#define M_ROWS  (NNODES * TT)   /* 180000 */
#define NCOLS   1024            /* 512 Q cols + 512 K cols */

#define RESID_SCALE    2048.0f          /* 2^11 */
#define RESID_INV      4.8828125e-4f    /* 2^-11 */

/* Scratch */
__device__ float g_qk[(size_t)M_ROWS * NCOLS];
__device__ __half g_As[2ull * M_ROWS * EMBED];   /* fp16 split planes of X  */
__device__ __half g_Bs[2ull * NCOLS * EMBED];    /* fp16 split planes of [Wq;Wk] */

/* ================= helpers ================= */
__device__ __forceinline__ uint32_t smem_u32(const void* p) {
    uint32_t a;
    asm("{ .reg .u64 t; cvta.to.shared.u64 t, %1; cvt.u32.u64 %0, t; }" : "=r"(a) : "l"(p));
    return a;
}
__device__ __forceinline__ void cp16(uint32_t dst, const void* src, bool pred) {
    int sz = pred ? 16 : 0;
    asm volatile("cp.async.cg.shared.global [%0], [%1], 16, %2;"
                 :: "r"(dst), "l"(src), "r"(sz) : "memory");
}
__device__ __forceinline__ void ldsm_x4(uint32_t* r, uint32_t addr) {
    asm volatile("ldmatrix.sync.aligned.m8n8.x4.shared.b16 {%0,%1,%2,%3}, [%4];"
                 : "=r"(r[0]), "=r"(r[1]), "=r"(r[2]), "=r"(r[3]) : "r"(addr));
}
__device__ __forceinline__ void mma_f16(float* c, const uint32_t* a, const uint32_t* b) {
    asm volatile("mma.sync.aligned.m16n8k16.row.col.f32.f16.f16.f32 "
                 "{%0,%1,%2,%3}, {%4,%5,%6,%7}, {%8,%9}, {%0,%1,%2,%3};"
                 : "+f"(c[0]), "+f"(c[1]), "+f"(c[2]), "+f"(c[3])
                 : "r"(a[0]), "r"(a[1]), "r"(a[2]), "r"(a[3]), "r"(b[0]), "r"(b[1]));
}

/* ========== fp16x2 RN split with scaled residual plane ==========
 * a0 = RN16(x);  a1' = RN16(2^11 * (x - a0))  (normal-range, no subnormals) */
__device__ __forceinline__ void split2s(float x, __half& a0, __half& a1) {
    a0 = __float2half_rn(x);
    a1 = __float2half_rn((x - __half2float(a0)) * RESID_SCALE);
}

/* ================= merged split kernel (A then B), float4-wide ========= */
#define A_QUADS ((size_t)M_ROWS * EMBED / 4)   /* 23,040,000 */
#define B_QUADS ((size_t)NCOLS * EMBED / 4)    /* 131,072 */

__device__ __forceinline__ void split_quad(float4 x, uint2& p0, uint2& p1) {
    __half a0, a1, b0, b1, c0, c1, d0, d1;
    split2s(x.x, a0, a1);
    split2s(x.y, b0, b1);
    split2s(x.z, c0, c1);
    split2s(x.w, d0, d1);
    __half2 h0 = __half2(a0, b0), h1 = __half2(c0, d0);
    __half2 h2 = __half2(a1, b1), h3 = __half2(c1, d1);
    p0.x = *(uint32_t*)&h0; p0.y = *(uint32_t*)&h1;
    p1.x = *(uint32_t*)&h2; p1.y = *(uint32_t*)&h3;
}

__global__ void split_kernel(const float* __restrict__ X,
                             const float* __restrict__ Wq,
                             const float* __restrict__ Wk) {
    size_t gid = (size_t)blockIdx.x * blockDim.x + threadIdx.x;
    if (gid < A_QUADS) {
        float4 x = ((const float4*)X)[gid];
        uint2 p0, p1;
        split_quad(x, p0, p1);
        const size_t SPQ = (size_t)M_ROWS * EMBED / 4;   /* quads per plane */
        ((uint2*)g_As)[gid] = p0;
        ((uint2*)g_As)[SPQ + gid] = p1;
    } else if (gid < A_QUADS + B_QUADS) {
        size_t p = gid - A_QUADS;
        size_t i = p * 4;
        size_t j = i >> 9;
        size_t k = i & 511;
        const float* src = (j < 512) ? (Wq + j * 512 + k) : (Wk + (j - 512) * 512 + k);
        float4 x = *(const float4*)src;
        uint2 p0, p1;
        split_quad(x, p0, p1);
        const size_t SPQ = (size_t)NCOLS * EMBED / 4;
        ((uint2*)g_Bs)[p] = p0;
        ((uint2*)g_Bs)[SPQ + p] = p1;
    }
}

/* ================= mma.sync fp16x2 GEMM, 3 products, dual-class =====
 * c_main: a0*b0.   c_rest: a0*b1' + a1'*b0   (both carry 2^11 factor).
 * result = c_main + (c_rest * 2^-11 + bias).
 * BM=64, BN=64, BK=32. 128 threads (4 warps, 2x2 warp grid, tile 32x32).
 * 3-stage cp.async pipeline, 4 CTAs/SM.  (unchanged from R9 - bit-exact) */
#define BK          32
#define KCHUNKS     (EMBED / BK)        /* 16 */
#define A_TILE_B    (64 * 64)           /* per split: 64 rows x 64 B */
#define B_TILE_B    (64 * 64)
#define STAGE_B     (2 * A_TILE_B + 2 * B_TILE_B)   /* 16 KB */
#define NSTAGE      3
#define SMEM_TOTAL  (NSTAGE * STAGE_B)              /* 48 KB */

__device__ __forceinline__ void load_chunk(uint32_t sb, int stage, int kc,
                                           int m0, int n0, int tid) {
    const size_t SPA = (size_t)M_ROWS * EMBED;
    const size_t SPB = (size_t)NCOLS * EMBED;
    uint32_t base = sb + stage * STAGE_B;
#pragma unroll
    for (int i = 0; i < 4; i++) {
        int o = tid + i * 128;
        int split = o >> 8;
        int rem = o & 255;
        int row = rem >> 2;
        int g = rem & 3;
        int gs = g ^ ((row >> 1) & 3);
        int m = m0 + row;
        bool v = (m < M_ROWS);
        const __half* src = g_As + split * SPA
                          + (size_t)(v ? m : 0) * EMBED + kc * BK + g * 8;
        cp16(base + split * A_TILE_B + row * 64 + gs * 16, src, v);
    }
#pragma unroll
    for (int i = 0; i < 4; i++) {
        int o = tid + i * 128;
        int split = o >> 8;
        int rem = o & 255;
        int row = rem >> 2;
        int g = rem & 3;
        int gs = g ^ ((row >> 1) & 3);
        const __half* src = g_Bs + split * SPB
                          + (size_t)(n0 + row) * EMBED + kc * BK + g * 8;
        cp16(base + 2 * A_TILE_B + split * B_TILE_B + row * 64 + gs * 16, src, true);
    }
    asm volatile("cp.async.commit_group;" ::: "memory");
}

__global__ __launch_bounds__(128, 4)
void qk_gemm_mma(const float* __restrict__ bq, const float* __restrict__ bk) {
    extern __shared__ char smem[];
    uint32_t sb = smem_u32(smem);
    const int tid = threadIdx.x;
    const int wid = tid >> 5;
    const int lane = tid & 31;
    const int m0 = blockIdx.y * 64;
    const int n0 = blockIdx.x * 64;
    const int warp_m = (wid >> 1) * 32;
    const int warp_n = (wid & 1) * 32;

    float c_main[2][4][4];
    float c_rest[2][4][4];
#pragma unroll
    for (int im = 0; im < 2; im++)
#pragma unroll
        for (int jn = 0; jn < 4; jn++)
#pragma unroll
            for (int q = 0; q < 4; q++) { c_main[im][jn][q] = 0.f; c_rest[im][jn][q] = 0.f; }

    load_chunk(sb, 0, 0, m0, n0, tid);
    load_chunk(sb, 1, 1, m0, n0, tid);

    const int a_r = (lane & 7) + ((lane >> 3) & 1) * 8;
    const int a_g = (lane >> 4) & 1;
    const int b_r = (lane & 7) + ((lane >> 4) & 1) * 8;
    const int b_g = (lane >> 3) & 1;

    for (int kc = 0; kc < KCHUNKS; kc++) {
        const int st = kc % NSTAGE;
        asm volatile("cp.async.wait_group 1;" ::: "memory");
        __syncthreads();

        if (kc + NSTAGE - 1 < KCHUNKS)
            load_chunk(sb, (kc + NSTAGE - 1) % NSTAGE, kc + NSTAGE - 1, m0, n0, tid);
        else
            asm volatile("cp.async.commit_group;" ::: "memory");

        const uint32_t abase = sb + st * STAGE_B;
        const uint32_t bbase = abase + 2 * A_TILE_B;

#pragma unroll
        for (int ks = 0; ks < 2; ks++) {
            uint32_t bf[2][2][4];
#pragma unroll
            for (int s = 0; s < 2; s++)
#pragma unroll
                for (int j2 = 0; j2 < 2; j2++) {
                    int row = warp_n + j2 * 16 + b_r;
                    int g = ks * 2 + b_g;
                    int gs = g ^ ((row >> 1) & 3);
                    ldsm_x4(bf[s][j2], bbase + s * B_TILE_B + row * 64 + gs * 16);
                }
            {
                uint32_t af[2][4];
#pragma unroll
                for (int im = 0; im < 2; im++) {
                    int row = warp_m + im * 16 + a_r;
                    int g = ks * 2 + a_g;
                    int gs = g ^ ((row >> 1) & 3);
                    ldsm_x4(af[im], abase + 0 * A_TILE_B + row * 64 + gs * 16);
                }
#pragma unroll
                for (int im = 0; im < 2; im++)
#pragma unroll
                    for (int jn = 0; jn < 4; jn++)
                        mma_f16(c_main[im][jn], af[im], &bf[0][jn >> 1][(jn & 1) * 2]);
#pragma unroll
                for (int im = 0; im < 2; im++)
#pragma unroll
                    for (int jn = 0; jn < 4; jn++)
                        mma_f16(c_rest[im][jn], af[im], &bf[1][jn >> 1][(jn & 1) * 2]);
            }
            {
                uint32_t af[2][4];
#pragma unroll
                for (int im = 0; im < 2; im++) {
                    int row = warp_m + im * 16 + a_r;
                    int g = ks * 2 + a_g;
                    int gs = g ^ ((row >> 1) & 3);
                    ldsm_x4(af[im], abase + 1 * A_TILE_B + row * 64 + gs * 16);
                }
#pragma unroll
                for (int im = 0; im < 2; im++)
#pragma unroll
                    for (int jn = 0; jn < 4; jn++)
                        mma_f16(c_rest[im][jn], af[im], &bf[0][jn >> 1][(jn & 1) * 2]);
            }
        }
    }

    const float* bias = (n0 < 512) ? (bq + n0) : (bk + (n0 - 512));
#pragma unroll
    for (int im = 0; im < 2; im++) {
#pragma unroll
        for (int jn = 0; jn < 4; jn++) {
            int col = warp_n + jn * 8 + (lane & 3) * 2;
            float b0 = bias[col], b1 = bias[col + 1];
            int row0 = m0 + warp_m + im * 16 + (lane >> 2);
            if (row0 < M_ROWS) {
                float2 v = make_float2(
                    c_main[im][jn][0] + fmaf(c_rest[im][jn][0], RESID_INV, b0),
                    c_main[im][jn][1] + fmaf(c_rest[im][jn][1], RESID_INV, b1));
                *(float2*)(g_qk + (size_t)row0 * NCOLS + n0 + col) = v;
            }
            int row1 = row0 + 8;
            if (row1 < M_ROWS) {
                float2 v = make_float2(
                    c_main[im][jn][2] + fmaf(c_rest[im][jn][2], RESID_INV, b0),
                    c_main[im][jn][3] + fmaf(c_rest[im][jn][3], RESID_INV, b1));
                *(float2*)(g_qk + (size_t)row1 * NCOLS + n0 + col) = v;
            }
        }
    }
}

/* ================= attention (V in registers, gate inlined) ========== */
#define EPAD (EMBED + 4)

__global__ __launch_bounds__(128)
void attn_kernel(const float* __restrict__ emb,
                 const float* __restrict__ ac,
                 const float* __restrict__ Wg,
                 const float* __restrict__ bg,
                 const int* __restrict__ batch,
                 float* __restrict__ out_ctx,
                 float* __restrict__ out_attn) {
    __shared__ float Qs[TT][EPAD];
    __shared__ float Ks[TT][EPAD];
    __shared__ float Ssc[HEADS][TT][TT];
    __shared__ float Sat[HEADS][TT][TT];
    __shared__ float Sg[TT];

    const int node = blockIdx.x;
    const int tid = threadIdx.x;

    const float4* qkb = (const float4*)(g_qk + (size_t)node * TT * NCOLS);
    const float4* vb  = (const float4*)(emb + (size_t)node * TT * EMBED);

    /* V column for this thread's fixed c4 = tid: straight to registers */
    float4 vreg[TT];
#pragma unroll
    for (int s = 0; s < TT; s++) vreg[s] = vb[s * 128 + tid];

    /* Q/K rows into smem */
#pragma unroll
    for (int t = 0; t < TT; t++) {
        float4 q = qkb[t * 256 + tid];
        float4 k = qkb[t * 256 + 128 + tid];
        ((float4*)Qs[t])[tid] = q;
        ((float4*)Ks[t])[tid] = k;
    }
    if (tid < TT) {
        int g = batch[node];
        float acc = bg[tid];
#pragma unroll
        for (int j = 0; j < 5; j++) acc += ac[g * 5 + j] * Wg[tid * 5 + j];
        Sg[tid] = acc;
    }
    __syncthreads();

    for (int task = tid; task < HEADS * TT * TT; task += 128) {
        int h = task / 36;
        int r = task % 36;
        int t = r / 6, s = r % 6;
        const float4* qp = (const float4*)&Qs[t][h * HDIM];
        const float4* kp = (const float4*)&Ks[s][h * HDIM];
        float a0 = 0.f;
#pragma unroll
        for (int d = 0; d < 16; d++) {
            float4 a = qp[d], b = kp[d];
            a0 += a.x * b.x + a.y * b.y + a.z * b.z + a.w * b.w;
        }
        Ssc[h][t][s] = a0 * 0.125f * Sg[s];
    }
    __syncthreads();

    if (tid < HEADS * TT) {
        int h = tid / 6, t = tid % 6;
        float sc[6], ab[6];
#pragma unroll
        for (int s = 0; s < 6; s++) {
            sc[s] = Ssc[h][t][s];
            ab[s] = fabsf(sc[s]);
        }
        bool keep[6];
        float mx = -INFINITY;
#pragma unroll
        for (int i = 0; i < 6; i++) {
            int rank = 0;
#pragma unroll
            for (int j = 0; j < 6; j++)
                rank += (ab[j] > ab[i]) || (ab[j] == ab[i] && j < i);
            keep[i] = (rank < 4);
            if (keep[i]) mx = fmaxf(mx, sc[i]);
        }
        float e[6], sum = 0.f;
#pragma unroll
        for (int i = 0; i < 6; i++) {
            e[i] = keep[i] ? expf(sc[i] - mx) : 0.f;
            sum += e[i];
        }
        float inv = 1.0f / sum;
        float* oat = out_attn + (size_t)node * (HEADS * TT * TT) + tid * 6;
#pragma unroll
        for (int i = 0; i < 6; i++) {
            float a = e[i] * inv;
            Sat[h][t][i] = a;
            oat[i] = a;
        }
    }
    __syncthreads();

    /* context: out[t][c4] = sum_s attn[h][t][s] * V[s][c4], h = tid>>4 */
    float4* octx = (float4*)(out_ctx + (size_t)node * TT * EMBED);
    const int h = tid >> 4;
#pragma unroll
    for (int t = 0; t < TT; t++) {
        float4 a4 = make_float4(0.f, 0.f, 0.f, 0.f);
#pragma unroll
        for (int s = 0; s < 6; s++) {
            float a = Sat[h][t][s];
            float4 v = vreg[s];
            a4.x += a * v.x; a4.y += a * v.y;
            a4.z += a * v.z; a4.w += a * v.w;
        }
        octx[t * 128 + tid] = a4;
    }
}

/* ================= launch ================= */
extern "C" void kernel_launch(void* const* d_in, const int* in_sizes, int n_in,
                              void* d_out, int out_size) {
    const float* emb   = (const float*)d_in[0];
    const float* ac    = (const float*)d_in[1];
    const float* Wk    = (const float*)d_in[2];
    const float* bk    = (const float*)d_in[3];
    const float* Wq    = (const float*)d_in[4];
    const float* bq    = (const float*)d_in[5];
    const float* Wg    = (const float*)d_in[6];
    const float* bg    = (const float*)d_in[7];
    const int*   batch = (const int*)d_in[8];

    float* out = (float*)d_out;
    float* out_ctx  = out;
    float* out_attn = out + (size_t)NNODES * TT * EMBED;

    size_t tot_quads = A_QUADS + B_QUADS;
    split_kernel<<<(unsigned)((tot_quads + 255) / 256), 256>>>(emb, Wq, Wk);

    cudaFuncSetAttribute(qk_gemm_mma, cudaFuncAttributeMaxDynamicSharedMemorySize, SMEM_TOTAL);
    qk_gemm_mma<<<dim3(NCOLS / 64, (M_ROWS + 63) / 64), 128, SMEM_TOTAL>>>(bq, bk);

    attn_kernel<<<NNODES, 128>>>(emb, ac, Wg, bg, batch, out_ctx, out_attn);
}